// round 6
// baseline (speedup 1.0000x reference)
#include <cuda_runtime.h>

// ---------------------------------------------------------------------------
// GASP_EGNN coordinate update on GB300 (sm_103a) — round 5 (SIMT, f32x2)
// out = coord + segment_sum( (coord[r]-coord[c])/(||.||+1) * MLP(h[r],h[c],ea), r)/100
//
// R5: weights pre-duplicated in smem as f32x2 (w,w) pairs -> k-step has ZERO
// register-splat MOVs: 2x LDS.128 dup-weights + 2x LDS.128 broadcast inputs
// + 16 fma2. 3-chunk input staging (64-row reusable buffer), 16 warps/SM.
// ---------------------------------------------------------------------------

#define HID  64
#define EIN  8
#define DIN  (2*HID + EIN)    // 136
#define EPW  16               // edges per warp
#define PAD  16               // floats per stage row
#define NWARPS 16
#define BUF_FLOATS (64*PAD)   // 1024 floats = 4KB per warp

typedef unsigned long long ull;

__device__ __forceinline__ ull pack2(float a, float b) {
    ull r; asm("mov.b64 %0, {%1,%2};" : "=l"(r) : "f"(a), "f"(b)); return r;
}
__device__ __forceinline__ void unpack2(ull p, float& a, float& b) {
    asm("mov.b64 {%0,%1}, %2;" : "=f"(a), "=f"(b) : "l"(p));
}
__device__ __forceinline__ ull fma2(ull a, ull b, ull c) {
    ull d; asm("fma.rn.f32x2 %0, %1, %2, %3;" : "=l"(d) : "l"(a), "l"(b), "l"(c)); return d;
}
__device__ __forceinline__ ull mul2(ull a, ull b) {
    ull d; asm("mul.rn.f32x2 %0, %1, %2;" : "=l"(d) : "l"(a), "l"(b)); return d;
}
__device__ __forceinline__ ull add2(ull a, ull b) {
    ull d; asm("add.rn.f32x2 %0, %1, %2;" : "=l"(d) : "l"(a), "l"(b)); return d;
}
__device__ __forceinline__ float silu1(float x) {
    return __fdividef(x, 1.0f + __expf(-x));
}
__device__ __forceinline__ ull silu2(ull p) {
    float a, b; unpack2(p, a, b);
    return pack2(silu1(a), silu1(b));
}

__global__ void egnn_init_out(const float* __restrict__ coord, float* __restrict__ out, int n) {
    int i = blockIdx.x * blockDim.x + threadIdx.x;
    if (i < n) out[i] = coord[i];
}

// smem: sW1d[136*64] ull, sW2d[64*64] ull, sB1d/sB2d/sW3d[64] ull, bufs
#define SMEM_BYTES ((DIN*HID + HID*HID + 3*HID) * 8 + NWARPS * BUF_FLOATS * 4)

// one k-step: 2 LDS.128 dup-weights + 2 LDS.128 inputs -> 16 fma2, no MOVs
#define KSTEP(WD, KIDX, ACC)                                                  \
    {                                                                         \
        const ulonglong2* wp = (const ulonglong2*)((WD) + (KIDX) * HID + c0); \
        ulonglong2 wA = wp[0], wB = wp[1];                                    \
        const ulonglong2* xp = (const ulonglong2*)(sBuf + (KIDX) * PAD + eg * 8); \
        ulonglong2 xa = xp[0], xb = xp[1];                                    \
        ACC[0][0]=fma2(xa.x,wA.x,ACC[0][0]); ACC[0][1]=fma2(xa.y,wA.x,ACC[0][1]); \
        ACC[0][2]=fma2(xb.x,wA.x,ACC[0][2]); ACC[0][3]=fma2(xb.y,wA.x,ACC[0][3]); \
        ACC[1][0]=fma2(xa.x,wA.y,ACC[1][0]); ACC[1][1]=fma2(xa.y,wA.y,ACC[1][1]); \
        ACC[1][2]=fma2(xb.x,wA.y,ACC[1][2]); ACC[1][3]=fma2(xb.y,wA.y,ACC[1][3]); \
        ACC[2][0]=fma2(xa.x,wB.x,ACC[2][0]); ACC[2][1]=fma2(xa.y,wB.x,ACC[2][1]); \
        ACC[2][2]=fma2(xb.x,wB.x,ACC[2][2]); ACC[2][3]=fma2(xb.y,wB.x,ACC[2][3]); \
        ACC[3][0]=fma2(xa.x,wB.y,ACC[3][0]); ACC[3][1]=fma2(xa.y,wB.y,ACC[3][1]); \
        ACC[3][2]=fma2(xb.x,wB.y,ACC[3][2]); ACC[3][3]=fma2(xb.y,wB.y,ACC[3][3]); \
    }

__global__ __launch_bounds__(512, 1)
void egnn_edge_kernel(
    const float* __restrict__ h, const float* __restrict__ coord,
    const int*   __restrict__ ei, const float* __restrict__ ea,
    const float* __restrict__ W1, const float* __restrict__ b1,
    const float* __restrict__ W2, const float* __restrict__ b2,
    const float* __restrict__ W3, float* __restrict__ out, int E)
{
    extern __shared__ ull smu[];
    ull* sW1d = smu;                         // [136][64] dup pairs
    ull* sW2d = sW1d + DIN * HID;            // [64][64]
    ull* sB1d = sW2d + HID * HID;
    ull* sB2d = sB1d + HID;
    ull* sW3d = sB2d + HID;
    float* sBufAll = (float*)(sW3d + HID);

    const int tid  = threadIdx.x;
    const int lane = tid & 31;
    const int wid  = tid >> 5;
    float* sBuf = sBufAll + wid * BUF_FLOATS;   // per-warp [64][16]

    // duplicate-pack weights into smem (once per CTA, persistent grid)
    for (int i = tid; i < DIN * HID; i += 512) { float v = W1[i]; sW1d[i] = pack2(v, v); }
    for (int i = tid; i < HID * HID; i += 512) { float v = W2[i]; sW2d[i] = pack2(v, v); }
    if (tid < HID) {
        float v1 = b1[tid], v2 = b2[tid], v3 = W3[tid];
        sB1d[tid] = pack2(v1, v1); sB2d[tid] = pack2(v2, v2); sW3d[tid] = pack2(v3, v3);
    }
    __syncthreads();

    const int cg = lane >> 1;     // 0..15 col group (4 cols)
    const int eg = lane & 1;      // edge half (8 edges)
    const int c0 = 4 * cg;

    const int nwarps  = gridDim.x * NWARPS;
    const int gwid    = blockIdx.x * NWARPS + wid;
    const int ngroups = E / EPW;
    const unsigned FULL = 0xffffffffu;

    const int e_st = lane & 15;   // staging edge
    const int part = lane >> 4;   // staging feature half

    for (int g = gwid; g < ngroups; g += nwarps) {
        const int ebase = g * EPW;

        // lanes 0..15: rn, lanes 16..31: cn
        int t;
        if (lane < 16) t = ei[ebase + lane];
        else           t = ei[E + ebase + lane - 16];

        const int node_r = __shfl_sync(FULL, t, e_st);
        const int node_c = __shfl_sync(FULL, t, 16 + e_st);

        ull a[4][4];
        {
            ull i0 = sB1d[c0], i1 = sB1d[c0+1], i2 = sB1d[c0+2], i3 = sB1d[c0+3];
            #pragma unroll
            for (int p = 0; p < 4; p++) { a[0][p]=i0; a[1][p]=i1; a[2][p]=i2; a[3][p]=i3; }
        }

        // ===== chunk A: h[row] -> buffer rows 0..63, W1d rows 0..63 =========
        {
            const float4* hr = (const float4*)(h + (size_t)node_r * HID + part * 32);
            float4 v[8];
            #pragma unroll
            for (int i = 0; i < 8; i++) v[i] = hr[i];
            #pragma unroll
            for (int i = 0; i < 8; i++) {
                int kb = part * 32 + i * 4;
                sBuf[(kb+0)*PAD + e_st] = v[i].x; sBuf[(kb+1)*PAD + e_st] = v[i].y;
                sBuf[(kb+2)*PAD + e_st] = v[i].z; sBuf[(kb+3)*PAD + e_st] = v[i].w;
            }
        }
        __syncwarp();
        #pragma unroll 8
        for (int k = 0; k < HID; k++) KSTEP(sW1d, k, a)
        __syncwarp();

        // ===== chunk B: h[col] -> buffer rows 0..63, W1d rows 64..127 =======
        {
            const float4* hc = (const float4*)(h + (size_t)node_c * HID + part * 32);
            float4 v[8];
            #pragma unroll
            for (int i = 0; i < 8; i++) v[i] = hc[i];
            #pragma unroll
            for (int i = 0; i < 8; i++) {
                int kb = part * 32 + i * 4;
                sBuf[(kb+0)*PAD + e_st] = v[i].x; sBuf[(kb+1)*PAD + e_st] = v[i].y;
                sBuf[(kb+2)*PAD + e_st] = v[i].z; sBuf[(kb+3)*PAD + e_st] = v[i].w;
            }
        }
        __syncwarp();
        {
            const ull* W = sW1d + 64 * HID;
            #pragma unroll 8
            for (int k = 0; k < HID; k++) KSTEP(W, k, a)
        }
        __syncwarp();

        // ===== chunk C: edge_attr -> buffer rows 0..7, W1d rows 128..135 ====
        {
            const int e2 = lane >> 1, half = lane & 1;
            float4 v = *(const float4*)(ea + (size_t)(ebase + e2) * EIN + half * 4);
            int kb = half * 4;
            sBuf[(kb+0)*PAD + e2] = v.x; sBuf[(kb+1)*PAD + e2] = v.y;
            sBuf[(kb+2)*PAD + e2] = v.z; sBuf[(kb+3)*PAD + e2] = v.w;
        }
        __syncwarp();
        {
            const ull* W = sW1d + 128 * HID;
            #pragma unroll
            for (int k = 0; k < EIN; k++) KSTEP(W, k, a)
        }
        __syncwarp();

        // ===== silu -> x1 into buffer rows 0..63 ============================
        #pragma unroll
        for (int j = 0; j < 4; j++)
            #pragma unroll
            for (int p = 0; p < 4; p++)
                *(ull*)(sBuf + (c0 + j) * PAD + eg * 8 + 2 * p) = silu2(a[j][p]);
        __syncwarp();

        // ===== layer 2: [16,64] x [64,64] ===================================
        ull d[4][4];
        {
            ull i0 = sB2d[c0], i1 = sB2d[c0+1], i2 = sB2d[c0+2], i3 = sB2d[c0+3];
            #pragma unroll
            for (int p = 0; p < 4; p++) { d[0][p]=i0; d[1][p]=i1; d[2][p]=i2; d[3][p]=i3; }
        }
        #pragma unroll 8
        for (int k = 0; k < HID; k++) KSTEP(sW2d, k, d)

        // ===== layer 3: silu(x2).W3, reduce across 16 col groups ============
        ull w30 = sW3d[c0], w31 = sW3d[c0+1], w32 = sW3d[c0+2], w33 = sW3d[c0+3];
        ull pp[4];
        #pragma unroll
        for (int p = 0; p < 4; p++) {
            ull s = mul2(silu2(d[0][p]), w30);
            s = fma2(silu2(d[1][p]), w31, s);
            s = fma2(silu2(d[2][p]), w32, s);
            s = fma2(silu2(d[3][p]), w33, s);
            pp[p] = s;
        }
        #pragma unroll
        for (int off = 2; off < 32; off <<= 1) {
            #pragma unroll
            for (int p = 0; p < 4; p++)
                pp[p] = add2(pp[p], __shfl_xor_sync(FULL, pp[p], off));
        }

        // ===== epilogue: 1 lane per edge (lanes 0..15) ======================
        const int e   = lane & 15;
        const int src = e >> 3;
        ull q0 = __shfl_sync(FULL, pp[0], src);
        ull q1 = __shfl_sync(FULL, pp[1], src);
        ull q2 = __shfl_sync(FULL, pp[2], src);
        ull q3 = __shfl_sync(FULL, pp[3], src);
        const int pidx = (e & 7) >> 1;
        ull qq = (pidx == 0) ? q0 : (pidx == 1) ? q1 : (pidx == 2) ? q2 : q3;
        float qlo, qhi; unpack2(qq, qlo, qhi);
        const float sc = (e & 1) ? qhi : qlo;

        const int rn = __shfl_sync(FULL, t, e);
        const int cn = __shfl_sync(FULL, t, 16 + e);

        if (lane < 16) {
            const float dx = coord[rn * 3 + 0] - coord[cn * 3 + 0];
            const float dy = coord[rn * 3 + 1] - coord[cn * 3 + 1];
            const float dz = coord[rn * 3 + 2] - coord[cn * 3 + 2];
            const float sq = dx * dx + dy * dy + dz * dz;
            const float norm = sqrtf(sq + 1e-8f);
            const float f = sc / ((norm + 1.0f) * 100.0f);
            atomicAdd(&out[rn * 3 + 0], dx * f);
            atomicAdd(&out[rn * 3 + 1], dy * f);
            atomicAdd(&out[rn * 3 + 2], dz * f);
        }
        __syncwarp();
    }
}

extern "C" void kernel_launch(void* const* d_in, const int* in_sizes, int n_in,
                              void* d_out, int out_size)
{
    const float* h     = (const float*)d_in[0];
    const float* coord = (const float*)d_in[1];
    const int*   ei    = (const int*)  d_in[2];
    const float* ea    = (const float*)d_in[3];
    const float* W1    = (const float*)d_in[4];
    const float* b1    = (const float*)d_in[5];
    const float* W2    = (const float*)d_in[6];
    const float* b2    = (const float*)d_in[7];
    const float* W3    = (const float*)d_in[8];
    float* out = (float*)d_out;

    const int E = in_sizes[3] / EIN;   // 1,600,000

    egnn_init_out<<<(out_size + 255) / 256, 256>>>(coord, out, out_size);

    cudaFuncSetAttribute(egnn_edge_kernel,
                         cudaFuncAttributeMaxDynamicSharedMemorySize, SMEM_BYTES);
    egnn_edge_kernel<<<148, 512, SMEM_BYTES>>>(h, coord, ei, ea,
                                               W1, b1, W2, b2, W3, out, E);
}

// round 7
// speedup vs baseline: 5.6913x; 5.6913x over previous
#include <cuda_runtime.h>
#include <cuda_bf16.h>
#include <cstdint>

// ---------------------------------------------------------------------------
// GASP_EGNN coordinate update on GB300 (sm_103a) — round 6: mma.sync bf16
// out = coord + segment_sum( (coord[r]-coord[c])/(||.||+1) * MLP(h[r],h[c],ea), r)/100
//
// Per warp-tile (16 edges): stage X=[h[rn]|h[cn]|ea|bias1|0pad] as bf16 in
// smem (stride 304B, ldmatrix-conflict-free), layer1 = 9x8 HMMA m16n8k16
// (K=144, bias folded at k=136), layer1 D-frags -> SiLU -> layer2 A-frags
// IN REGISTERS (m16n8 D layout == m16n8k16 A layout), layer2 = 5x8 HMMA
// (K=80, bias tile synthesized), SiLU -> dot W3 -> shfl reduce -> atomics.
// W1/W2 pre-arranged in smem as per-lane B-fragments (LDS.64, no conflicts).
// ---------------------------------------------------------------------------

#define HID   64
#define EIN   8
#define EPW   16
#define XSTRIDE 304                 // bytes per X row (152 bf16): conflict-free
#define XBYTES  (16 * XSTRIDE)      // 4864 B per warp
#define NWARPS  16
#define NT1   9                     // layer1 k-tiles (K=144)
#define NT2   5                     // layer2 k-tiles (K=80)

typedef uint32_t u32;
typedef unsigned long long ull;

__device__ __forceinline__ u32 smem_u32(const void* p) {
    u32 a;
    asm("{ .reg .u64 t; cvta.to.shared.u64 t, %1; cvt.u32.u64 %0, t; }"
        : "=r"(a) : "l"(p));
    return a;
}
__device__ __forceinline__ u32 cvt2(float a, float b) {
    __nv_bfloat162 t = __floats2bfloat162_rn(a, b);
    return *(u32*)&t;
}
__device__ __forceinline__ float silu1(float x) {
    float t;
    asm("tanh.approx.f32 %0, %1;" : "=f"(t) : "f"(0.5f * x));
    return 0.5f * x * (1.0f + t);
}
__device__ __forceinline__ void ldsm4(u32& r0, u32& r1, u32& r2, u32& r3, u32 addr) {
    asm volatile("ldmatrix.sync.aligned.m8n8.x4.shared.b16 {%0,%1,%2,%3}, [%4];"
                 : "=r"(r0), "=r"(r1), "=r"(r2), "=r"(r3) : "r"(addr));
}
__device__ __forceinline__ void mma16816(float* d, u32 a0, u32 a1, u32 a2, u32 a3,
                                         u32 b0, u32 b1) {
    asm volatile("mma.sync.aligned.m16n8k16.row.col.f32.bf16.bf16.f32 "
                 "{%0,%1,%2,%3}, {%4,%5,%6,%7}, {%8,%9}, {%0,%1,%2,%3};"
                 : "+f"(d[0]), "+f"(d[1]), "+f"(d[2]), "+f"(d[3])
                 : "r"(a0), "r"(a1), "r"(a2), "r"(a3), "r"(b0), "r"(b1));
}

__global__ void egnn_init_out(const float* __restrict__ coord, float* __restrict__ out, int n) {
    int i = blockIdx.x * blockDim.x + threadIdx.x;
    if (i < n) out[i] = coord[i];
}

// smem layout (bytes): sB1f 9*8*32*8=18432 | sB2f 5*8*32*8=10240 | sW3 256 |
//                      X stages 16*4864=77824  -> total 106752
#define SB1_OFF  0
#define SB2_OFF  18432
#define SW3_OFF  (18432 + 10240)
#define SX_OFF   (SW3_OFF + 256)
#define SMEM_BYTES (SX_OFF + NWARPS * XBYTES)

__global__ __launch_bounds__(512, 1)
void egnn_mma_kernel(
    const float* __restrict__ h, const float* __restrict__ coord,
    const int*   __restrict__ ei, const float* __restrict__ ea,
    const float* __restrict__ W1, const float* __restrict__ b1,
    const float* __restrict__ W2, const float* __restrict__ b2,
    const float* __restrict__ W3, float* __restrict__ out, int E)
{
    extern __shared__ char sm[];
    uint2* sB1f = (uint2*)(sm + SB1_OFF);   // [t][j][lane] -> (breg0, breg1)
    uint2* sB2f = (uint2*)(sm + SB2_OFF);
    float* sW3  = (float*)(sm + SW3_OFF);

    const int tid  = threadIdx.x;
    const int lane = tid & 31;
    const int wid  = tid >> 5;
    char* sXw = sm + SX_OFF + wid * XBYTES;     // this warp's X stage [16][304B]

    // ---- precompute B fragments for W1 (K=144: rows 136=b1, 137..143=0) ----
    for (int idx = tid; idx < NT1 * 8 * 32; idx += 512) {
        int t = idx >> 8, j = (idx >> 5) & 7, l = idx & 31;
        int n  = j * 8 + (l >> 2);
        int k0 = t * 16 + (l & 3) * 2;
        float v0 = (k0     < 136) ? W1[k0 * HID + n]       : ((k0     == 136) ? b1[n] : 0.0f);
        float v1 = (k0 + 1 < 136) ? W1[(k0 + 1) * HID + n] : ((k0 + 1 == 136) ? b1[n] : 0.0f);
        int k1 = k0 + 8;
        float v2 = (k1     < 136) ? W1[k1 * HID + n]       : ((k1     == 136) ? b1[n] : 0.0f);
        float v3 = (k1 + 1 < 136) ? W1[(k1 + 1) * HID + n] : ((k1 + 1 == 136) ? b1[n] : 0.0f);
        sB1f[idx] = make_uint2(cvt2(v0, v1), cvt2(v2, v3));
    }
    // ---- precompute B fragments for W2 (K=80: row 64=b2, 65..79=0) ---------
    for (int idx = tid; idx < NT2 * 8 * 32; idx += 512) {
        int t = idx >> 8, j = (idx >> 5) & 7, l = idx & 31;
        int n  = j * 8 + (l >> 2);
        int k0 = t * 16 + (l & 3) * 2;
        float v0 = (k0     < 64) ? W2[k0 * HID + n]       : ((k0     == 64) ? b2[n] : 0.0f);
        float v1 = (k0 + 1 < 64) ? W2[(k0 + 1) * HID + n] : ((k0 + 1 == 64) ? b2[n] : 0.0f);
        int k1 = k0 + 8;
        float v2 = (k1     < 64) ? W2[k1 * HID + n]       : ((k1     == 64) ? b2[n] : 0.0f);
        float v3 = (k1 + 1 < 64) ? W2[(k1 + 1) * HID + n] : ((k1 + 1 == 64) ? b2[n] : 0.0f);
        sB2f[idx] = make_uint2(cvt2(v0, v1), cvt2(v2, v3));
    }
    if (tid < HID) sW3[tid] = W3[tid];

    // ---- X pad cols: col136=1 (layer1 bias), 137..143=0 (write once) -------
    if (lane < 16) {
        *(ull*)(sXw + lane * XSTRIDE + 272) = 0x3F80ULL;   // bf16(1.0),0,0,0
        *(ull*)(sXw + lane * XSTRIDE + 280) = 0ULL;
    }
    __syncthreads();

    const unsigned FULL = 0xffffffffu;
    const int nwarps  = gridDim.x * NWARPS;
    const int gwid    = blockIdx.x * NWARPS + wid;
    const int ngroups = E / EPW;

    // ldmatrix row base for this lane (row = lane&15, +16B for k-hi matrices)
    const u32 lm_base = smem_u32(sXw) + (u32)(lane & 15) * XSTRIDE
                        + ((lane & 16) ? 16u : 0u);
    const int l4 = lane & 3;          // quad position
    const u32 bias_a = (l4 == 0) ? cvt2(1.0f, 0.0f) : 0u;  // layer2 bias A-frag

    for (int g = gwid; g < ngroups; g += nwarps) {
        const int ebase = g * EPW;

        // lanes 0..15: rn, 16..31: cn
        int t;
        if (lane < 16) t = ei[ebase + lane];
        else           t = ei[E + ebase + lane - 16];

        // ================= stage X (bf16) ==================================
        // instr i handles edge i: 4 lines (2 nodes x 2 halves), 8 lanes/line
        {
            const int sel     = lane >> 3;        // 0..3
            const int nodesel = sel >> 1;         // 0=rn 1=cn
            const int half    = sel & 1;
            const int qi      = lane & 7;
            #pragma unroll
            for (int i = 0; i < 16; i++) {
                int node = __shfl_sync(FULL, t, nodesel * 16 + i);
                float4 v = *(const float4*)(h + (size_t)node * HID + half * 32 + qi * 4);
                *(uint2*)(sXw + i * XSTRIDE + nodesel * 128 + half * 64 + qi * 8)
                    = make_uint2(cvt2(v.x, v.y), cvt2(v.z, v.w));
            }
            // edge_attr: 16 edges x 8 floats, fully coalesced
            float4 va = *(const float4*)(ea + (size_t)ebase * EIN + lane * 4);
            *(uint2*)(sXw + (lane >> 1) * XSTRIDE + 256 + (lane & 1) * 8)
                = make_uint2(cvt2(va.x, va.y), cvt2(va.z, va.w));
        }
        __syncwarp();

        // ================= layer 1: 9 k-tiles x 8 n-tiles ==================
        float dacc[8][4];
        #pragma unroll
        for (int j = 0; j < 8; j++)
            #pragma unroll
            for (int q = 0; q < 4; q++) dacc[j][q] = 0.0f;

        #pragma unroll
        for (int tt = 0; tt < NT1; tt++) {
            u32 a0, a1, a2, a3;
            ldsm4(a0, a1, a2, a3, lm_base + tt * 32);
            #pragma unroll
            for (int j = 0; j < 8; j++) {
                uint2 b = sB1f[(tt * 8 + j) * 32 + lane];
                mma16816(dacc[j], a0, a1, a2, a3, b.x, b.y);
            }
        }
        __syncwarp();

        // ===== SiLU(D1) -> layer2 A-fragments, entirely in registers =======
        u32 a2f[NT2][4];
        #pragma unroll
        for (int j = 0; j < 8; j++) {
            int t2 = j >> 1, hi = (j & 1) * 2;
            a2f[t2][hi + 0] = cvt2(silu1(dacc[j][0]), silu1(dacc[j][1]));
            a2f[t2][hi + 1] = cvt2(silu1(dacc[j][2]), silu1(dacc[j][3]));
        }
        a2f[4][0] = bias_a; a2f[4][1] = bias_a; a2f[4][2] = 0; a2f[4][3] = 0;

        // ================= layer 2: 5 k-tiles x 8 n-tiles ==================
        float eacc[8][4];
        #pragma unroll
        for (int j = 0; j < 8; j++)
            #pragma unroll
            for (int q = 0; q < 4; q++) eacc[j][q] = 0.0f;

        #pragma unroll
        for (int tt = 0; tt < NT2; tt++) {
            #pragma unroll
            for (int j = 0; j < 8; j++) {
                uint2 b = sB2f[(tt * 8 + j) * 32 + lane];
                mma16816(eacc[j], a2f[tt][0], a2f[tt][1], a2f[tt][2], a2f[tt][3],
                         b.x, b.y);
            }
        }

        // ===== SiLU(D2) . W3, reduce over quad =============================
        float s_lo = 0.0f, s_hi = 0.0f;     // rows lane/4 and lane/4+8
        #pragma unroll
        for (int j = 0; j < 8; j++) {
            int c = j * 8 + l4 * 2;
            float w0 = sW3[c], w1 = sW3[c + 1];
            s_lo += silu1(eacc[j][0]) * w0 + silu1(eacc[j][1]) * w1;
            s_hi += silu1(eacc[j][2]) * w0 + silu1(eacc[j][3]) * w1;
        }
        s_lo += __shfl_xor_sync(FULL, s_lo, 1);
        s_lo += __shfl_xor_sync(FULL, s_lo, 2);
        s_hi += __shfl_xor_sync(FULL, s_hi, 1);
        s_hi += __shfl_xor_sync(FULL, s_hi, 2);

        // ===== epilogue: lane e (0..15) owns edge e ========================
        const int src4 = (lane & 7) * 4;
        float slo_b = __shfl_sync(FULL, s_lo, src4);
        float shi_b = __shfl_sync(FULL, s_hi, src4);
        const float sc = (lane < 8) ? slo_b : shi_b;

        const int rn = __shfl_sync(FULL, t, lane & 15);
        const int cn = __shfl_sync(FULL, t, 16 + (lane & 15));

        if (lane < 16) {
            const float dx = coord[rn * 3 + 0] - coord[cn * 3 + 0];
            const float dy = coord[rn * 3 + 1] - coord[cn * 3 + 1];
            const float dz = coord[rn * 3 + 2] - coord[cn * 3 + 2];
            const float nrm = sqrtf(dx * dx + dy * dy + dz * dz + 1e-8f);
            const float f = sc / ((nrm + 1.0f) * 100.0f);
            atomicAdd(&out[rn * 3 + 0], dx * f);
            atomicAdd(&out[rn * 3 + 1], dy * f);
            atomicAdd(&out[rn * 3 + 2], dz * f);
        }
        __syncwarp();
    }
}

extern "C" void kernel_launch(void* const* d_in, const int* in_sizes, int n_in,
                              void* d_out, int out_size)
{
    const float* h     = (const float*)d_in[0];
    const float* coord = (const float*)d_in[1];
    const int*   ei    = (const int*)  d_in[2];
    const float* ea    = (const float*)d_in[3];
    const float* W1    = (const float*)d_in[4];
    const float* b1    = (const float*)d_in[5];
    const float* W2    = (const float*)d_in[6];
    const float* b2    = (const float*)d_in[7];
    const float* W3    = (const float*)d_in[8];
    float* out = (float*)d_out;

    const int E = in_sizes[3] / EIN;   // 1,600,000 (divisible by 16)

    egnn_init_out<<<(out_size + 255) / 256, 256>>>(coord, out, out_size);

    cudaFuncSetAttribute(egnn_mma_kernel,
                         cudaFuncAttributeMaxDynamicSharedMemorySize, SMEM_BYTES);
    egnn_mma_kernel<<<148, 512, SMEM_BYTES>>>(h, coord, ei, ea,
                                              W1, b1, W2, b2, W3, out, E);
}